// round 2
// baseline (speedup 1.0000x reference)
#include <cuda_runtime.h>
#include <mma.h>
#include <math.h>
#include <stdint.h>

using namespace nvcuda;

#define NTOK   8192          // B*T = 4*2048
#define NE     8             // experts
#define DMODEL 1024
#define DFF    4096
#define OUT_ELEMS ((size_t)NTOK * DMODEL)   // 8388608 floats, gate1 follows

// ---------------- device scratch (no allocations allowed) ----------------
__device__ int   g_cnt[NE];
__device__ int   g_tok[NE][NTOK];
__device__ float g_gate[NE][NTOK];
__device__ float g_hbuf[(size_t)NTOK * DFF];   // 128 MB fp32 scratch, reused across experts

// ---------------- cp.async helpers ----------------
__device__ __forceinline__ unsigned smem_u32(const void* p) {
    return (unsigned)__cvta_generic_to_shared(p);
}
__device__ __forceinline__ void cp_async16(void* dst_smem, const void* src_gmem) {
    asm volatile("cp.async.cg.shared.global [%0], [%1], 16;\n"
                 :: "r"(smem_u32(dst_smem)), "l"(src_gmem));
}
__device__ __forceinline__ void cp_commit() {
    asm volatile("cp.async.commit_group;\n");
}
template<int N>
__device__ __forceinline__ void cp_wait() {
    asm volatile("cp.async.wait_group %0;\n" :: "n"(N));
}

// ---------------- gating: logits, softmax(gate1), top-2, expert lists ----------------
__device__ __forceinline__ void accum_seg(const float* __restrict__ f, int len,
                                          const float* __restrict__ wg_base,
                                          float acc[8], int tid)
{
    for (int l = tid; l < len; l += 256) {
        float v = f[l];
        const float4* w = (const float4*)(wg_base + (size_t)l * 8);
        float4 w0 = w[0], w1 = w[1];
        acc[0] += v * w0.x; acc[1] += v * w0.y; acc[2] += v * w0.z; acc[3] += v * w0.w;
        acc[4] += v * w1.x; acc[5] += v * w1.y; acc[6] += v * w1.z; acc[7] += v * w1.w;
    }
}

__global__ void gating_kernel(const float* __restrict__ x,
                              const float* __restrict__ dt,
                              const float* __restrict__ dd,
                              const float* __restrict__ drg,
                              const float* __restrict__ de,
                              const float* __restrict__ city,
                              const float* __restrict__ Wg,
                              const float* __restrict__ bg,
                              const int*   __restrict__ city_index,
                              float* __restrict__ gate1_out)
{
    int t = blockIdx.x;
    int tid = threadIdx.x;
    float acc[8] = {0,0,0,0,0,0,0,0};

    const float* cemb = city + (*city_index) * 32;

    accum_seg(x   + (size_t)t * 1024, 1024, Wg + (size_t)0    * 8, acc, tid);
    accum_seg(cemb,                     32, Wg + (size_t)1024 * 8, acc, tid);
    accum_seg(dt  + (size_t)t * 256,   256, Wg + (size_t)1056 * 8, acc, tid);
    accum_seg(dd  + (size_t)t * 256,   256, Wg + (size_t)1312 * 8, acc, tid);
    accum_seg(drg + (size_t)t * 128,   128, Wg + (size_t)1568 * 8, acc, tid);
    accum_seg(de  + (size_t)t * 128,   128, Wg + (size_t)1696 * 8, acc, tid);

    __shared__ float red[8][256];
    #pragma unroll
    for (int e = 0; e < 8; e++) red[e][tid] = acc[e];
    __syncthreads();
    for (int s = 128; s > 0; s >>= 1) {
        if (tid < s) {
            #pragma unroll
            for (int e = 0; e < 8; e++) red[e][tid] += red[e][tid + s];
        }
        __syncthreads();
    }

    if (tid == 0) {
        float lg[8];
        #pragma unroll
        for (int e = 0; e < 8; e++) lg[e] = red[e][0] + bg[e];

        float l0 = lg[0]; int i0 = 0;
        #pragma unroll
        for (int e = 1; e < 8; e++) if (lg[e] > l0) { l0 = lg[e]; i0 = e; }
        float l1 = -1e30f; int i1 = -1;
        #pragma unroll
        for (int e = 0; e < 8; e++) if (e != i0 && lg[e] > l1) { l1 = lg[e]; i1 = e; }

        float ssum = 0.f;
        float ex[8];
        #pragma unroll
        for (int e = 0; e < 8; e++) { ex[e] = __expf(lg[e] - l0); ssum += ex[e]; }
        float inv = 1.0f / ssum;
        #pragma unroll
        for (int e = 0; e < 8; e++) gate1_out[(size_t)t * 8 + e] = ex[e] * inv;

        float e1 = __expf(l1 - l0);
        float g0 = 1.0f / (1.0f + e1);
        float g1 = e1   / (1.0f + e1);

        int p0 = atomicAdd(&g_cnt[i0], 1);
        g_tok[i0][p0] = t; g_gate[i0][p0] = g0;
        int p1 = atomicAdd(&g_cnt[i1], 1);
        g_tok[i1][p1] = t; g_gate[i1][p1] = g1;
    }
}

// ---------------- tiled TF32 wmma GEMMs, 2-stage cp.async pipeline ----------------
// Tile: BM=128 BN=128 BK=32, 256 threads = 8 warps (2x4), warp tile 64x32.
// Dynamic smem: 2 stages x (As 16KB + Bs 16KB) = 64KB. Epilogue aliases stage 0.

#define AS_ELEMS (128 * 32)
#define BS_ELEMS (32 * 128)
#define STAGE_ELEMS (AS_ELEMS + BS_ELEMS)
#define SMEM_BYTES (2 * STAGE_ELEMS * 4)

// copies one k-tile (A: gathered rows of act, B: weight rows) into stage buffer
__device__ __forceinline__ void issue_tile(float* As, float* Bs,
                                           const float* __restrict__ asrc, // row base (+k applied)
                                           const float* __restrict__ Wk,   // W + k0*ldw + n0
                                           int ldw, int tid)
{
    int ar   = tid >> 1;              // 0..127
    int aseg = (tid & 1) * 16;        // 0 or 16 floats
    cp_async16(As + ar * 32 + aseg +  0, asrc + (size_t)ar * 0 + aseg +  0); // placeholder (unused)
}

template<int KDIM>
__device__ __forceinline__ void gemm_mainloop(
    float* smem,
    const float* __restrict__ a_base,  // per-thread gathered A row base pointer (row ar)
    const float* __restrict__ w_base,  // W + n0 (+bc applied below), row stride ldw
    int ldw, int tid,
    wmma::fragment<wmma::accumulator, 16, 16, 8, float> (&cfr)[4][2],
    int wm, int wn)
{
    const int KT = KDIM / 32;
    int ar   = tid >> 1;
    int aseg = (tid & 1) * 16;
    int br   = tid >> 3;              // 0..31
    int bc   = (tid & 7) * 16;        // 0..112

    float* As[2] = { smem,                    smem + STAGE_ELEMS };
    float* Bs[2] = { smem + AS_ELEMS,         smem + STAGE_ELEMS + AS_ELEMS };

    // prologue: stage 0
    {
        const float* ap = a_base + aseg;             // k0 = 0
        cp_async16(As[0] + ar * 32 + aseg +  0, ap +  0);
        cp_async16(As[0] + ar * 32 + aseg +  4, ap +  4);
        cp_async16(As[0] + ar * 32 + aseg +  8, ap +  8);
        cp_async16(As[0] + ar * 32 + aseg + 12, ap + 12);
        const float* bp = w_base + (size_t)br * ldw + bc;
        cp_async16(Bs[0] + br * 128 + bc +  0, bp +  0);
        cp_async16(Bs[0] + br * 128 + bc +  4, bp +  4);
        cp_async16(Bs[0] + br * 128 + bc +  8, bp +  8);
        cp_async16(Bs[0] + br * 128 + bc + 12, bp + 12);
        cp_commit();
    }

    for (int kt = 0; kt < KT; kt++) {
        int cur = kt & 1;
        if (kt + 1 < KT) {
            int nxt = cur ^ 1;
            int k1 = (kt + 1) * 32;
            const float* ap = a_base + k1 + aseg;
            cp_async16(As[nxt] + ar * 32 + aseg +  0, ap +  0);
            cp_async16(As[nxt] + ar * 32 + aseg +  4, ap +  4);
            cp_async16(As[nxt] + ar * 32 + aseg +  8, ap +  8);
            cp_async16(As[nxt] + ar * 32 + aseg + 12, ap + 12);
            const float* bp = w_base + (size_t)(k1 + br) * ldw + bc;
            cp_async16(Bs[nxt] + br * 128 + bc +  0, bp +  0);
            cp_async16(Bs[nxt] + br * 128 + bc +  4, bp +  4);
            cp_async16(Bs[nxt] + br * 128 + bc +  8, bp +  8);
            cp_async16(Bs[nxt] + br * 128 + bc + 12, bp + 12);
            cp_commit();
            cp_wait<1>();
        } else {
            cp_wait<0>();
        }
        __syncthreads();

        float* Ac = As[cur];
        float* Bc = Bs[cur];
        #pragma unroll
        for (int ks = 0; ks < 32; ks += 8) {
            wmma::fragment<wmma::matrix_b, 16, 16, 8, wmma::precision::tf32, wmma::row_major> bfr[2];
            #pragma unroll
            for (int ni = 0; ni < 2; ni++) {
                wmma::load_matrix_sync(bfr[ni], Bc + ks * 128 + wn * 32 + ni * 16, 128);
                #pragma unroll
                for (int i = 0; i < bfr[ni].num_elements; i++)
                    bfr[ni].x[i] = wmma::__float_to_tf32(bfr[ni].x[i]);
            }
            #pragma unroll
            for (int mi = 0; mi < 4; mi++) {
                wmma::fragment<wmma::matrix_a, 16, 16, 8, wmma::precision::tf32, wmma::row_major> afr;
                wmma::load_matrix_sync(afr, Ac + (wm * 64 + mi * 16) * 32 + ks, 32);
                #pragma unroll
                for (int i = 0; i < afr.num_elements; i++)
                    afr.x[i] = wmma::__float_to_tf32(afr.x[i]);
                wmma::mma_sync(cfr[mi][0], afr, bfr[0], cfr[mi][0]);
                wmma::mma_sync(cfr[mi][1], afr, bfr[1], cfr[mi][1]);
            }
        }
        __syncthreads();
    }
}

__global__ void __launch_bounds__(256)
ffn1_kernel(int e,
            const float* __restrict__ x,
            const float* __restrict__ W1,
            const float* __restrict__ b1)
{
    extern __shared__ float smem[];

    int Ne = g_cnt[e];
    int m0 = blockIdx.x * 128;
    if (m0 >= Ne) return;
    int n0 = blockIdx.y * 128;

    int tid  = threadIdx.x;
    int warp = tid >> 5;
    int lane = tid & 31;
    int wm = warp >> 2;   // 0..1
    int wn = warp & 3;    // 0..3

    const float* W = W1 + (size_t)e * DMODEL * DFF;

    int ar   = tid >> 1;
    int arow = m0 + ar;
    int tok  = (arow < Ne) ? g_tok[e][arow] : 0;
    const float* a_base = x + (size_t)tok * DMODEL;   // per-thread row base

    wmma::fragment<wmma::accumulator, 16, 16, 8, float> cfr[4][2];
    #pragma unroll
    for (int mi = 0; mi < 4; mi++)
        #pragma unroll
        for (int ni = 0; ni < 2; ni++) wmma::fill_fragment(cfr[mi][ni], 0.0f);

    gemm_mainloop<DMODEL>(smem, a_base, W + n0, DFF, tid, cfr, wm, wn);

    // epilogue: + b1, tanh-GELU, write h scratch. Cst aliases pipeline smem.
    float* Cw = smem + warp * (16 * 24);
    const float* b1e = b1 + (size_t)e * DFF;
    #pragma unroll
    for (int mi = 0; mi < 4; mi++) {
        #pragma unroll
        for (int ni = 0; ni < 2; ni++) {
            wmma::store_matrix_sync(Cw, cfr[mi][ni], 24, wmma::mem_row_major);
            __syncwarp();
            int r0  = wm * 64 + mi * 16;
            int c0g = n0 + wn * 32 + ni * 16;
            #pragma unroll
            for (int j = 0; j < 8; j++) {
                int idx = lane * 8 + j;          // 0..255
                int rr = idx >> 4, cc = idx & 15;
                float v = Cw[rr * 24 + cc] + b1e[c0g + cc];
                float u = 0.7978845608028654f * (v + 0.044715f * v * v * v);
                float g = 0.5f * v * (1.0f + tanhf(u));
                g_hbuf[(size_t)(m0 + r0 + rr) * DFF + c0g + cc] = g;
            }
            __syncwarp();
        }
    }
}

__global__ void __launch_bounds__(256)
ffn2_kernel(int e,
            const float* __restrict__ W2,
            const float* __restrict__ b2,
            float* __restrict__ out)
{
    extern __shared__ float smem[];

    int Ne = g_cnt[e];
    int m0 = blockIdx.x * 128;
    if (m0 >= Ne) return;
    int n0 = blockIdx.y * 128;

    int tid  = threadIdx.x;
    int warp = tid >> 5;
    int lane = tid & 31;
    int wm = warp >> 2;
    int wn = warp & 3;

    const float* W = W2 + (size_t)e * DFF * DMODEL;

    int ar = tid >> 1;
    const float* a_base = g_hbuf + (size_t)(m0 + ar) * DFF;

    wmma::fragment<wmma::accumulator, 16, 16, 8, float> cfr[4][2];
    #pragma unroll
    for (int mi = 0; mi < 4; mi++)
        #pragma unroll
        for (int ni = 0; ni < 2; ni++) wmma::fill_fragment(cfr[mi][ni], 0.0f);

    gemm_mainloop<DFF>(smem, a_base, W + n0, DMODEL, tid, cfr, wm, wn);

    float* Cw = smem + warp * (16 * 24);
    const float* b2e = b2 + (size_t)e * DMODEL;
    #pragma unroll
    for (int mi = 0; mi < 4; mi++) {
        #pragma unroll
        for (int ni = 0; ni < 2; ni++) {
            wmma::store_matrix_sync(Cw, cfr[mi][ni], 24, wmma::mem_row_major);
            __syncwarp();
            int r0  = wm * 64 + mi * 16;
            int c0g = n0 + wn * 32 + ni * 16;
            #pragma unroll
            for (int j = 0; j < 8; j++) {
                int idx = lane * 8 + j;
                int rr = idx >> 4, cc = idx & 15;
                int grow = m0 + r0 + rr;
                if (grow < Ne) {
                    int tok = g_tok[e][grow];
                    float gt = g_gate[e][grow];
                    float v  = Cw[rr * 24 + cc] + b2e[c0g + cc];
                    atomicAdd(&out[(size_t)tok * DMODEL + c0g + cc], gt * v);
                }
            }
            __syncwarp();
        }
    }
}

// ---------------- launch ----------------
extern "C" void kernel_launch(void* const* d_in, const int* in_sizes, int n_in,
                              void* d_out, int out_size)
{
    const float* x    = (const float*)d_in[0];
    const float* dt   = (const float*)d_in[1];
    const float* dd   = (const float*)d_in[2];
    const float* drg  = (const float*)d_in[3];
    const float* de   = (const float*)d_in[4];
    const float* city = (const float*)d_in[5];
    const float* Wg   = (const float*)d_in[6];
    const float* bg   = (const float*)d_in[7];
    const float* W1   = (const float*)d_in[8];
    const float* b1   = (const float*)d_in[9];
    const float* W2   = (const float*)d_in[10];
    const float* b2   = (const float*)d_in[11];
    const int*   cidx = (const int*)  d_in[12];

    float* out   = (float*)d_out;
    float* gate1 = out + OUT_ELEMS;

    static bool attr_done = false;
    if (!attr_done) {
        cudaFuncSetAttribute(ffn1_kernel, cudaFuncAttributeMaxDynamicSharedMemorySize, SMEM_BYTES);
        cudaFuncSetAttribute(ffn2_kernel, cudaFuncAttributeMaxDynamicSharedMemorySize, SMEM_BYTES);
        attr_done = true;
    }

    void* cnt_ptr = nullptr;
    cudaGetSymbolAddress(&cnt_ptr, g_cnt);
    cudaMemsetAsync(cnt_ptr, 0, sizeof(int) * NE, 0);
    cudaMemsetAsync(out, 0, OUT_ELEMS * sizeof(float), 0);

    gating_kernel<<<NTOK, 256>>>(x, dt, dd, drg, de, city, Wg, bg, cidx, gate1);

    dim3 g1(NTOK / 128, DFF / 128);      // (64, 32), blocks early-exit past Ne
    dim3 g2(NTOK / 128, DMODEL / 128);   // (64, 8)
    for (int e = 0; e < NE; e++) {
        ffn1_kernel<<<g1, 256, SMEM_BYTES>>>(e, x, W1, b1);
        ffn2_kernel<<<g2, 256, SMEM_BYTES>>>(e, W2, b2, out);
    }
}

// round 5
// speedup vs baseline: 1.5855x; 1.5855x over previous
#include <cuda_runtime.h>
#include <mma.h>
#include <math.h>
#include <stdint.h>

using namespace nvcuda;

#define NTOK   8192
#define NE     8
#define DMODEL 1024
#define DFF    4096
#define OUT_ELEMS ((size_t)NTOK * DMODEL)
#define MAXROWS (NTOK * 2)          // top-2: total expert-token pairs
#define MAXTILES 136                // ceil-sum of per-expert 128-tiles <= 16384/128 + 8

// ---------------- device scratch ----------------
__device__ int   g_cnt[NE];
__device__ int   g_off[NE + 1];
__device__ int   g_tok[NE][NTOK];
__device__ float g_gate[NE][NTOK];
__device__ int   g_tile_e[MAXTILES];
__device__ int   g_tile_m0[MAXTILES];
__device__ int   g_ntiles;
__device__ float g_hbuf[(size_t)(MAXROWS + 128) * DFF];   // +128 row pad for tail reads

// ---------------- cp.async helpers ----------------
__device__ __forceinline__ unsigned smem_u32(const void* p) {
    return (unsigned)__cvta_generic_to_shared(p);
}
__device__ __forceinline__ void cp_async16(void* dst_smem, const void* src_gmem) {
    asm volatile("cp.async.cg.shared.global [%0], [%1], 16;\n"
                 :: "r"(smem_u32(dst_smem)), "l"(src_gmem));
}
__device__ __forceinline__ void cp_commit() {
    asm volatile("cp.async.commit_group;\n");
}
template<int N>
__device__ __forceinline__ void cp_wait() {
    asm volatile("cp.async.wait_group %0;\n" :: "n"(N));
}

// ---------------- gating ----------------
__device__ __forceinline__ void accum_seg(const float* __restrict__ f, int len,
                                          const float* __restrict__ wg_base,
                                          float acc[8], int tid)
{
    for (int l = tid; l < len; l += 256) {
        float v = f[l];
        const float4* w = (const float4*)(wg_base + (size_t)l * 8);
        float4 w0 = w[0], w1 = w[1];
        acc[0] += v * w0.x; acc[1] += v * w0.y; acc[2] += v * w0.z; acc[3] += v * w0.w;
        acc[4] += v * w1.x; acc[5] += v * w1.y; acc[6] += v * w1.z; acc[7] += v * w1.w;
    }
}

__global__ void gating_kernel(const float* __restrict__ x,
                              const float* __restrict__ dt,
                              const float* __restrict__ dd,
                              const float* __restrict__ drg,
                              const float* __restrict__ de,
                              const float* __restrict__ city,
                              const float* __restrict__ Wg,
                              const float* __restrict__ bg,
                              const int*   __restrict__ city_index,
                              float* __restrict__ gate1_out)
{
    int t = blockIdx.x;
    int tid = threadIdx.x;
    float acc[8] = {0,0,0,0,0,0,0,0};

    const float* cemb = city + (*city_index) * 32;

    accum_seg(x   + (size_t)t * 1024, 1024, Wg + (size_t)0    * 8, acc, tid);
    accum_seg(cemb,                     32, Wg + (size_t)1024 * 8, acc, tid);
    accum_seg(dt  + (size_t)t * 256,   256, Wg + (size_t)1056 * 8, acc, tid);
    accum_seg(dd  + (size_t)t * 256,   256, Wg + (size_t)1312 * 8, acc, tid);
    accum_seg(drg + (size_t)t * 128,   128, Wg + (size_t)1568 * 8, acc, tid);
    accum_seg(de  + (size_t)t * 128,   128, Wg + (size_t)1696 * 8, acc, tid);

    __shared__ float red[8][256];
    #pragma unroll
    for (int e = 0; e < 8; e++) red[e][tid] = acc[e];
    __syncthreads();
    for (int s = 128; s > 0; s >>= 1) {
        if (tid < s) {
            #pragma unroll
            for (int e = 0; e < 8; e++) red[e][tid] += red[e][tid + s];
        }
        __syncthreads();
    }

    if (tid == 0) {
        float lg[8];
        #pragma unroll
        for (int e = 0; e < 8; e++) lg[e] = red[e][0] + bg[e];

        float l0 = lg[0]; int i0 = 0;
        #pragma unroll
        for (int e = 1; e < 8; e++) if (lg[e] > l0) { l0 = lg[e]; i0 = e; }
        float l1 = -1e30f; int i1 = -1;
        #pragma unroll
        for (int e = 0; e < 8; e++) if (e != i0 && lg[e] > l1) { l1 = lg[e]; i1 = e; }

        float ssum = 0.f;
        float ex[8];
        #pragma unroll
        for (int e = 0; e < 8; e++) { ex[e] = __expf(lg[e] - l0); ssum += ex[e]; }
        float inv = 1.0f / ssum;
        #pragma unroll
        for (int e = 0; e < 8; e++) gate1_out[(size_t)t * 8 + e] = ex[e] * inv;

        float e1 = __expf(l1 - l0);
        float g0 = 1.0f / (1.0f + e1);
        float g1 = e1   / (1.0f + e1);

        int p0 = atomicAdd(&g_cnt[i0], 1);
        g_tok[i0][p0] = t; g_gate[i0][p0] = g0;
        int p1 = atomicAdd(&g_cnt[i1], 1);
        g_tok[i1][p1] = t; g_gate[i1][p1] = g1;
    }
}

// ---------------- schedule: prefix sums + tile table ----------------
__global__ void schedule_kernel()
{
    if (threadIdx.x == 0 && blockIdx.x == 0) {
        int off = 0, nt = 0;
        for (int e = 0; e < NE; e++) {
            g_off[e] = off;
            int c = g_cnt[e];
            int t = (c + 127) >> 7;
            for (int i = 0; i < t; i++) {
                g_tile_e[nt]  = e;
                g_tile_m0[nt] = i << 7;
                nt++;
            }
            off += c;
        }
        g_off[NE] = off;
        g_ntiles = nt;
    }
}

// ---------------- tiled TF32 wmma GEMMs ----------------
// Block 128x128x32, 8 warps (2x4), warp tile 64x32.
// Padded smem: A stride 36 floats, B stride 132 floats (conflict-free).
// 3-stage cp.async pipeline, one __syncthreads per k-tile.

#define A_LD 36
#define B_LD 132
#define AS_ELEMS (128 * A_LD)            // 4608
#define BS_ELEMS (32 * B_LD)             // 4224
#define STAGE_ELEMS (AS_ELEMS + BS_ELEMS)
#define NSTAGE 3
#define SMEM_BYTES (NSTAGE * STAGE_ELEMS * 4)   // 105984

__device__ __forceinline__ void issue_stage(float* As, float* Bs,
                                            const float* __restrict__ a_base, int k0,
                                            const float* __restrict__ w_base, int ldw,
                                            int ar, int aseg, int br, int bc)
{
    const float* ap = a_base + k0 + aseg;
    float* ad = As + ar * A_LD + aseg;
    cp_async16(ad +  0, ap +  0);
    cp_async16(ad +  4, ap +  4);
    cp_async16(ad +  8, ap +  8);
    cp_async16(ad + 12, ap + 12);
    const float* bp = w_base + (size_t)(k0 + br) * ldw + bc;
    float* bd = Bs + br * B_LD + bc;
    cp_async16(bd +  0, bp +  0);
    cp_async16(bd +  4, bp +  4);
    cp_async16(bd +  8, bp +  8);
    cp_async16(bd + 12, bp + 12);
}

template<int KDIM>
__device__ __forceinline__ void gemm_mainloop(
    float* smem,
    const float* __restrict__ a_base,   // per-thread gathered A row base (row ar)
    const float* __restrict__ w_base,   // W + n0, row stride ldw
    int ldw, int tid,
    wmma::fragment<wmma::accumulator, 16, 16, 8, float> (&cfr)[4][2],
    int wm, int wn)
{
    const int KT = KDIM / 32;
    int ar   = tid >> 1;
    int aseg = (tid & 1) * 16;
    int br   = tid >> 3;
    int bc   = (tid & 7) * 16;

    float* As[NSTAGE]; float* Bs[NSTAGE];
    #pragma unroll
    for (int s = 0; s < NSTAGE; s++) {
        As[s] = smem + s * STAGE_ELEMS;
        Bs[s] = smem + s * STAGE_ELEMS + AS_ELEMS;
    }

    // prologue: stages 0, 1
    issue_stage(As[0], Bs[0], a_base, 0,  w_base, ldw, ar, aseg, br, bc);
    cp_commit();
    issue_stage(As[1], Bs[1], a_base, 32, w_base, ldw, ar, aseg, br, bc);
    cp_commit();

    for (int kt = 0; kt < KT; kt++) {
        cp_wait<1>();          // groups G0..Gkt complete -> stage kt resident
        __syncthreads();       // all threads' stage-kt copies visible; stage kt-1 fully consumed

        // issue stage kt+2 into buffer (kt+2)%3 == (kt-1)%3 — consumed a barrier ago
        int ks2 = kt + 2;
        if (ks2 < KT) {
            int buf = ks2 % NSTAGE;
            issue_stage(As[buf], Bs[buf], a_base, ks2 * 32, w_base, ldw, ar, aseg, br, bc);
        }
        cp_commit();           // uniform commit (possibly empty) keeps wait accounting exact

        float* Ac = As[kt % NSTAGE];
        float* Bc = Bs[kt % NSTAGE];
        #pragma unroll
        for (int ks = 0; ks < 32; ks += 8) {
            wmma::fragment<wmma::matrix_b, 16, 16, 8, wmma::precision::tf32, wmma::row_major> bfr[2];
            #pragma unroll
            for (int ni = 0; ni < 2; ni++) {
                wmma::load_matrix_sync(bfr[ni], Bc + ks * B_LD + wn * 32 + ni * 16, B_LD);
                #pragma unroll
                for (int i = 0; i < bfr[ni].num_elements; i++)
                    bfr[ni].x[i] = wmma::__float_to_tf32(bfr[ni].x[i]);
            }
            #pragma unroll
            for (int mi = 0; mi < 4; mi++) {
                wmma::fragment<wmma::matrix_a, 16, 16, 8, wmma::precision::tf32, wmma::row_major> afr;
                wmma::load_matrix_sync(afr, Ac + (wm * 64 + mi * 16) * A_LD + ks, A_LD);
                #pragma unroll
                for (int i = 0; i < afr.num_elements; i++)
                    afr.x[i] = wmma::__float_to_tf32(afr.x[i]);
                wmma::mma_sync(cfr[mi][0], afr, bfr[0], cfr[mi][0]);
                wmma::mma_sync(cfr[mi][1], afr, bfr[1], cfr[mi][1]);
            }
        }
    }
    __syncthreads();   // protect smem before epilogue aliasing
}

__global__ void __launch_bounds__(256, 2)
ffn1_kernel(const float* __restrict__ x,
            const float* __restrict__ W1,
            const float* __restrict__ b1)
{
    extern __shared__ float smem[];

    int tile = blockIdx.x;
    if (tile >= g_ntiles) return;
    int e   = g_tile_e[tile];
    int m0  = g_tile_m0[tile];
    int cnt = g_cnt[e];
    int gbase = g_off[e] + m0;
    int n0 = blockIdx.y * 128;

    int tid  = threadIdx.x;
    int warp = tid >> 5;
    int lane = tid & 31;
    int wm = warp >> 2;
    int wn = warp & 3;

    const float* W = W1 + (size_t)e * DMODEL * DFF;

    int ar   = tid >> 1;
    int lrow = m0 + ar;
    int tok  = g_tok[e][lrow < cnt ? lrow : (cnt - 1)];
    const float* a_base = x + (size_t)tok * DMODEL;

    wmma::fragment<wmma::accumulator, 16, 16, 8, float> cfr[4][2];
    #pragma unroll
    for (int mi = 0; mi < 4; mi++)
        #pragma unroll
        for (int ni = 0; ni < 2; ni++) wmma::fill_fragment(cfr[mi][ni], 0.0f);

    gemm_mainloop<DMODEL>(smem, a_base, W + n0, DFF, tid, cfr, wm, wn);

    // epilogue: + b1, tanh-GELU, write h scratch
    float* Cw = smem + warp * (16 * 24);
    const float* b1e = b1 + (size_t)e * DFF;
    #pragma unroll
    for (int mi = 0; mi < 4; mi++) {
        #pragma unroll
        for (int ni = 0; ni < 2; ni++) {
            wmma::store_matrix_sync(Cw, cfr[mi][ni], 24, wmma::mem_row_major);
            __syncwarp();
            int r0  = wm * 64 + mi * 16;
            int c0g = n0 + wn * 32 + ni * 16;
            #pragma unroll
            for (int j = 0; j < 8; j++) {
                int idx = lane * 8 + j;
                int rr = idx >> 4, cc = idx & 15;
                int lr = m0 + r0 + rr;
                if (lr < cnt) {
                    float v = Cw[rr * 24 + cc] + b1e[c0g + cc];
                    float u = 0.7978845608028654f * (v + 0.044715f * v * v * v);
                    // 0.5*v*(1+tanh(u)) == v / (1 + exp(-2u))
                    float g = v / (1.0f + __expf(-2.0f * u));
                    g_hbuf[(size_t)(gbase + r0 + rr) * DFF + c0g + cc] = g;
                }
            }
            __syncwarp();
        }
    }
}

__global__ void __launch_bounds__(256, 2)
ffn2_kernel(const float* __restrict__ W2,
            const float* __restrict__ b2,
            float* __restrict__ out)
{
    extern __shared__ float smem[];

    int tile = blockIdx.x;
    if (tile >= g_ntiles) return;
    int e   = g_tile_e[tile];
    int m0  = g_tile_m0[tile];
    int cnt = g_cnt[e];
    int gbase = g_off[e] + m0;
    int n0 = blockIdx.y * 128;

    int tid  = threadIdx.x;
    int warp = tid >> 5;
    int lane = tid & 31;
    int wm = warp >> 2;
    int wn = warp & 3;

    const float* W = W2 + (size_t)e * DFF * DMODEL;

    int ar = tid >> 1;
    const float* a_base = g_hbuf + (size_t)(gbase + ar) * DFF;

    wmma::fragment<wmma::accumulator, 16, 16, 8, float> cfr[4][2];
    #pragma unroll
    for (int mi = 0; mi < 4; mi++)
        #pragma unroll
        for (int ni = 0; ni < 2; ni++) wmma::fill_fragment(cfr[mi][ni], 0.0f);

    gemm_mainloop<DFF>(smem, a_base, W + n0, DMODEL, tid, cfr, wm, wn);

    float* Cw = smem + warp * (16 * 24);
    const float* b2e = b2 + (size_t)e * DMODEL;
    #pragma unroll
    for (int mi = 0; mi < 4; mi++) {
        #pragma unroll
        for (int ni = 0; ni < 2; ni++) {
            wmma::store_matrix_sync(Cw, cfr[mi][ni], 24, wmma::mem_row_major);
            __syncwarp();
            int r0  = wm * 64 + mi * 16;
            int c0g = n0 + wn * 32 + ni * 16;
            #pragma unroll
            for (int j = 0; j < 8; j++) {
                int idx = lane * 8 + j;
                int rr = idx >> 4, cc = idx & 15;
                int lr = m0 + r0 + rr;
                if (lr < cnt) {
                    int tok  = g_tok[e][lr];
                    float gt = g_gate[e][lr];
                    float v  = Cw[rr * 24 + cc] + b2e[c0g + cc];
                    atomicAdd(&out[(size_t)tok * DMODEL + c0g + cc], gt * v);
                }
            }
            __syncwarp();
        }
    }
}

// ---------------- launch ----------------
extern "C" void kernel_launch(void* const* d_in, const int* in_sizes, int n_in,
                              void* d_out, int out_size)
{
    const float* x    = (const float*)d_in[0];
    const float* dt   = (const float*)d_in[1];
    const float* dd   = (const float*)d_in[2];
    const float* drg  = (const float*)d_in[3];
    const float* de   = (const float*)d_in[4];
    const float* city = (const float*)d_in[5];
    const float* Wg   = (const float*)d_in[6];
    const float* bg   = (const float*)d_in[7];
    const float* W1   = (const float*)d_in[8];
    const float* b1   = (const float*)d_in[9];
    const float* W2   = (const float*)d_in[10];
    const float* b2   = (const float*)d_in[11];
    const int*   cidx = (const int*)  d_in[12];

    float* out   = (float*)d_out;
    float* gate1 = out + OUT_ELEMS;

    cudaFuncSetAttribute(ffn1_kernel, cudaFuncAttributeMaxDynamicSharedMemorySize, SMEM_BYTES);
    cudaFuncSetAttribute(ffn2_kernel, cudaFuncAttributeMaxDynamicSharedMemorySize, SMEM_BYTES);

    void* cnt_ptr = nullptr;
    cudaGetSymbolAddress(&cnt_ptr, g_cnt);
    cudaMemsetAsync(cnt_ptr, 0, sizeof(int) * NE, 0);
    cudaMemsetAsync(out, 0, OUT_ELEMS * sizeof(float), 0);

    gating_kernel<<<NTOK, 256>>>(x, dt, dd, drg, de, city, Wg, bg, cidx, gate1);
    schedule_kernel<<<1, 32>>>();

    dim3 g1(MAXTILES, DFF / 128);      // (136, 32)
    dim3 g2(MAXTILES, DMODEL / 128);   // (136, 8)
    ffn1_kernel<<<g1, 256, SMEM_BYTES>>>(x, W1, b1);
    ffn2_kernel<<<g2, 256, SMEM_BYTES>>>(W2, b2, out);
}

// round 13
// speedup vs baseline: 1.6673x; 1.0516x over previous
#include <cuda_runtime.h>
#include <mma.h>
#include <math.h>
#include <stdint.h>

using namespace nvcuda;

#define NTOK   8192
#define NE     8
#define DMODEL 1024
#define DFF    4096
#define OUT_ELEMS ((size_t)NTOK * DMODEL)
#define MAXROWS (NTOK * 2)
#define MAXTILES 136

// ---------------- device scratch ----------------
__device__ int   g_cnt[NE];
__device__ int   g_off[NE + 1];
__device__ int   g_tok[NE][NTOK];
__device__ float g_gate[NE][NTOK];
__device__ int   g_tile_e[MAXTILES];
__device__ int   g_tile_m0[MAXTILES];
__device__ int   g_ntiles;
__device__ float g_hbuf[(size_t)(MAXROWS + 128) * DFF];   // tf32-RN h scratch (+pad rows)
__device__ float g_xr[(size_t)NTOK * DMODEL];             // tf32-RN x
__device__ float g_w1r[(size_t)NE * DMODEL * DFF];        // tf32-RN W1 (same layout)
__device__ float g_w2r[(size_t)NE * DFF * DMODEL];        // tf32-RN W2 (same layout)

// ---------------- helpers ----------------
__device__ __forceinline__ unsigned smem_u32(const void* p) {
    return (unsigned)__cvta_generic_to_shared(p);
}
__device__ __forceinline__ void cp_async16(void* dst_smem, const void* src_gmem) {
    asm volatile("cp.async.cg.shared.global [%0], [%1], 16;\n"
                 :: "r"(smem_u32(dst_smem)), "l"(src_gmem));
}
__device__ __forceinline__ void cp_commit() { asm volatile("cp.async.commit_group;\n"); }
template<int N> __device__ __forceinline__ void cp_wait() {
    asm volatile("cp.async.wait_group %0;\n" :: "n"(N));
}
__device__ __forceinline__ float to_tf32(float x) {
    float r;
    asm("cvt.rna.tf32.f32 %0, %1;" : "=f"(r) : "f"(x));
    return r;
}
__device__ __forceinline__ float gelu_f(float v) {
    float u = 0.7978845608028654f * (v + 0.044715f * v * v * v);
    return v / (1.0f + __expf(-2.0f * u));   // == 0.5*v*(1+tanh(u))
}

// ---------------- gating ----------------
__device__ __forceinline__ void accum_seg(const float* __restrict__ f, int len,
                                          const float* __restrict__ wg_base,
                                          float acc[8], int tid)
{
    for (int l = tid; l < len; l += 256) {
        float v = f[l];
        const float4* w = (const float4*)(wg_base + (size_t)l * 8);
        float4 w0 = w[0], w1 = w[1];
        acc[0] += v * w0.x; acc[1] += v * w0.y; acc[2] += v * w0.z; acc[3] += v * w0.w;
        acc[4] += v * w1.x; acc[5] += v * w1.y; acc[6] += v * w1.z; acc[7] += v * w1.w;
    }
}

__global__ void gating_kernel(const float* __restrict__ x,
                              const float* __restrict__ dt,
                              const float* __restrict__ dd,
                              const float* __restrict__ drg,
                              const float* __restrict__ de,
                              const float* __restrict__ city,
                              const float* __restrict__ Wg,
                              const float* __restrict__ bg,
                              const int*   __restrict__ city_index,
                              float* __restrict__ gate1_out)
{
    int t = blockIdx.x;
    int tid = threadIdx.x;
    float acc[8] = {0,0,0,0,0,0,0,0};
    const float* cemb = city + (*city_index) * 32;

    accum_seg(x   + (size_t)t * 1024, 1024, Wg + (size_t)0    * 8, acc, tid);
    accum_seg(cemb,                     32, Wg + (size_t)1024 * 8, acc, tid);
    accum_seg(dt  + (size_t)t * 256,   256, Wg + (size_t)1056 * 8, acc, tid);
    accum_seg(dd  + (size_t)t * 256,   256, Wg + (size_t)1312 * 8, acc, tid);
    accum_seg(drg + (size_t)t * 128,   128, Wg + (size_t)1568 * 8, acc, tid);
    accum_seg(de  + (size_t)t * 128,   128, Wg + (size_t)1696 * 8, acc, tid);

    __shared__ float red[8][256];
    #pragma unroll
    for (int e = 0; e < 8; e++) red[e][tid] = acc[e];
    __syncthreads();
    for (int s = 128; s > 0; s >>= 1) {
        if (tid < s) {
            #pragma unroll
            for (int e = 0; e < 8; e++) red[e][tid] += red[e][tid + s];
        }
        __syncthreads();
    }

    if (tid == 0) {
        float lg[8];
        #pragma unroll
        for (int e = 0; e < 8; e++) lg[e] = red[e][0] + bg[e];

        float l0 = lg[0]; int i0 = 0;
        #pragma unroll
        for (int e = 1; e < 8; e++) if (lg[e] > l0) { l0 = lg[e]; i0 = e; }
        float l1 = -1e30f; int i1 = -1;
        #pragma unroll
        for (int e = 0; e < 8; e++) if (e != i0 && lg[e] > l1) { l1 = lg[e]; i1 = e; }

        float ssum = 0.f, ex[8];
        #pragma unroll
        for (int e = 0; e < 8; e++) { ex[e] = __expf(lg[e] - l0); ssum += ex[e]; }
        float inv = 1.0f / ssum;
        #pragma unroll
        for (int e = 0; e < 8; e++) gate1_out[(size_t)t * 8 + e] = ex[e] * inv;

        float e1 = __expf(l1 - l0);
        float g0 = 1.0f / (1.0f + e1);
        float g1 = e1   / (1.0f + e1);

        int p0 = atomicAdd(&g_cnt[i0], 1);
        g_tok[i0][p0] = t; g_gate[i0][p0] = g0;
        int p1 = atomicAdd(&g_cnt[i1], 1);
        g_tok[i1][p1] = t; g_gate[i1][p1] = g1;
    }
}

__global__ void schedule_kernel()
{
    if (threadIdx.x == 0 && blockIdx.x == 0) {
        int off = 0, nt = 0;
        for (int e = 0; e < NE; e++) {
            g_off[e] = off;
            int c = g_cnt[e];
            int t = (c + 127) >> 7;
            for (int i = 0; i < t; i++) { g_tile_e[nt] = e; g_tile_m0[nt] = i << 7; nt++; }
            off += c;
        }
        g_off[NE] = off;
        g_ntiles = nt;
    }
}

// ---------------- tf32-RN rounding copies ----------------
__global__ void round_copy_kernel(const float* __restrict__ src, float* __restrict__ dst)
{
    size_t i = (size_t)blockIdx.x * blockDim.x + threadIdx.x;   // float4 index
    float4 v = ((const float4*)src)[i];
    v.x = to_tf32(v.x); v.y = to_tf32(v.y); v.z = to_tf32(v.z); v.w = to_tf32(v.w);
    ((float4*)dst)[i] = v;
}

// ---------------- tiled TF32 wmma GEMMs ----------------
// Block 128x128x32, 8 warps (2x4), warp tile 64x32.
// Padded smem: A stride 36, B stride 132 (conflict-free). 3-stage cp.async.
// Operands pre-rounded to tf32-RN -> NO per-element cvt in the mainloop.

#define A_LD 36
#define B_LD 132
#define AS_ELEMS (128 * A_LD)
#define BS_ELEMS (32 * B_LD)
#define STAGE_ELEMS (AS_ELEMS + BS_ELEMS)
#define NSTAGE 3
#define SMEM_BYTES (NSTAGE * STAGE_ELEMS * 4)   // 105984

__device__ __forceinline__ void issue_stage(float* As, float* Bs,
                                            const float* __restrict__ a_base, int k0,
                                            const float* __restrict__ w_base, int ldw,
                                            int ar, int aseg, int br, int bc)
{
    const float* ap = a_base + k0 + aseg;
    float* ad = As + ar * A_LD + aseg;
    cp_async16(ad +  0, ap +  0);
    cp_async16(ad +  4, ap +  4);
    cp_async16(ad +  8, ap +  8);
    cp_async16(ad + 12, ap + 12);
    const float* bp = w_base + (size_t)(k0 + br) * ldw + bc;
    float* bd = Bs + br * B_LD + bc;
    cp_async16(bd +  0, bp +  0);
    cp_async16(bd +  4, bp +  4);
    cp_async16(bd +  8, bp +  8);
    cp_async16(bd + 12, bp + 12);
}

template<int KDIM>
__device__ __forceinline__ void gemm_mainloop(
    float* smem,
    const float* __restrict__ a_base,
    const float* __restrict__ w_base,
    int ldw, int tid,
    wmma::fragment<wmma::accumulator, 16, 16, 8, float> (&cfr)[4][2],
    int wm, int wn)
{
    const int KT = KDIM / 32;
    int ar   = tid >> 1;
    int aseg = (tid & 1) * 16;
    int br   = tid >> 3;
    int bc   = (tid & 7) * 16;

    float* As[NSTAGE]; float* Bs[NSTAGE];
    #pragma unroll
    for (int s = 0; s < NSTAGE; s++) {
        As[s] = smem + s * STAGE_ELEMS;
        Bs[s] = smem + s * STAGE_ELEMS + AS_ELEMS;
    }

    issue_stage(As[0], Bs[0], a_base, 0,  w_base, ldw, ar, aseg, br, bc);
    cp_commit();
    issue_stage(As[1], Bs[1], a_base, 32, w_base, ldw, ar, aseg, br, bc);
    cp_commit();

    for (int kt = 0; kt < KT; kt++) {
        cp_wait<1>();
        __syncthreads();

        int ks2 = kt + 2;
        if (ks2 < KT) {
            int buf = ks2 % NSTAGE;
            issue_stage(As[buf], Bs[buf], a_base, ks2 * 32, w_base, ldw, ar, aseg, br, bc);
        }
        cp_commit();

        float* Ac = As[kt % NSTAGE];
        float* Bc = Bs[kt % NSTAGE];
        #pragma unroll
        for (int ks = 0; ks < 32; ks += 8) {
            // operands are pre-rounded tf32-RN: no per-element cvt needed
            wmma::fragment<wmma::matrix_b, 16, 16, 8, wmma::precision::tf32, wmma::row_major> bfr[2];
            wmma::load_matrix_sync(bfr[0], Bc + ks * B_LD + wn * 32 +  0, B_LD);
            wmma::load_matrix_sync(bfr[1], Bc + ks * B_LD + wn * 32 + 16, B_LD);
            #pragma unroll
            for (int mi = 0; mi < 4; mi++) {
                wmma::fragment<wmma::matrix_a, 16, 16, 8, wmma::precision::tf32, wmma::row_major> afr;
                wmma::load_matrix_sync(afr, Ac + (wm * 64 + mi * 16) * A_LD + ks, A_LD);
                wmma::mma_sync(cfr[mi][0], afr, bfr[0], cfr[mi][0]);
                wmma::mma_sync(cfr[mi][1], afr, bfr[1], cfr[mi][1]);
            }
        }
    }
    __syncthreads();   // protect smem before epilogue aliasing
}

__global__ void __launch_bounds__(256, 2)
ffn1_kernel(const float* __restrict__ b1)
{
    extern __shared__ float smem[];

    int tile = blockIdx.x;
    if (tile >= g_ntiles) return;
    int e   = g_tile_e[tile];
    int m0  = g_tile_m0[tile];
    int cnt = g_cnt[e];
    int gbase = g_off[e] + m0;
    int n0 = blockIdx.y * 128;

    int tid  = threadIdx.x;
    int warp = tid >> 5;
    int lane = tid & 31;
    int wm = warp >> 2;
    int wn = warp & 3;

    const float* W = g_w1r + (size_t)e * DMODEL * DFF;

    int ar   = tid >> 1;
    int lrow = m0 + ar;
    int tok  = g_tok[e][lrow < cnt ? lrow : (cnt - 1)];
    const float* a_base = g_xr + (size_t)tok * DMODEL;

    wmma::fragment<wmma::accumulator, 16, 16, 8, float> cfr[4][2];
    #pragma unroll
    for (int mi = 0; mi < 4; mi++)
        #pragma unroll
        for (int ni = 0; ni < 2; ni++) wmma::fill_fragment(cfr[mi][ni], 0.0f);

    gemm_mainloop<DMODEL>(smem, a_base, W + n0, DFF, tid, cfr, wm, wn);

    // epilogue: + b1, GELU, round to tf32-RN, write h scratch
    float* Cw = smem + warp * (16 * 24);
    const float* b1e = b1 + (size_t)e * DFF;
    #pragma unroll
    for (int mi = 0; mi < 4; mi++) {
        #pragma unroll
        for (int ni = 0; ni < 2; ni++) {
            wmma::store_matrix_sync(Cw, cfr[mi][ni], 24, wmma::mem_row_major);
            __syncwarp();
            int r0  = wm * 64 + mi * 16;
            int c0g = n0 + wn * 32 + ni * 16;
            #pragma unroll
            for (int j = 0; j < 8; j++) {
                int idx = lane * 8 + j;
                int rr = idx >> 4, cc = idx & 15;
                int lr = m0 + r0 + rr;
                if (lr < cnt) {
                    float v = Cw[rr * 24 + cc] + b1e[c0g + cc];
                    g_hbuf[(size_t)(gbase + r0 + rr) * DFF + c0g + cc] = to_tf32(gelu_f(v));
                }
            }
            __syncwarp();
        }
    }
}

__global__ void __launch_bounds__(256, 2)
ffn2_kernel(const float* __restrict__ b2, float* __restrict__ out)
{
    extern __shared__ float smem[];

    int tile = blockIdx.x;
    if (tile >= g_ntiles) return;
    int e   = g_tile_e[tile];
    int m0  = g_tile_m0[tile];
    int cnt = g_cnt[e];
    int gbase = g_off[e] + m0;
    int n0 = blockIdx.y * 128;

    int tid  = threadIdx.x;
    int warp = tid >> 5;
    int lane = tid & 31;
    int wm = warp >> 2;
    int wn = warp & 3;

    const float* W = g_w2r + (size_t)e * DFF * DMODEL;

    int ar = tid >> 1;
    const float* a_base = g_hbuf + (size_t)(gbase + ar) * DFF;

    wmma::fragment<wmma::accumulator, 16, 16, 8, float> cfr[4][2];
    #pragma unroll
    for (int mi = 0; mi < 4; mi++)
        #pragma unroll
        for (int ni = 0; ni < 2; ni++) wmma::fill_fragment(cfr[mi][ni], 0.0f);

    gemm_mainloop<DFF>(smem, a_base, W + n0, DMODEL, tid, cfr, wm, wn);

    float* Cw = smem + warp * (16 * 24);
    const float* b2e = b2 + (size_t)e * DMODEL;
    #pragma unroll
    for (int mi = 0; mi < 4; mi++) {
        #pragma unroll
        for (int ni = 0; ni < 2; ni++) {
            wmma::store_matrix_sync(Cw, cfr[mi][ni], 24, wmma::mem_row_major);
            __syncwarp();
            int r0  = wm * 64 + mi * 16;
            int c0g = n0 + wn * 32 + ni * 16;
            #pragma unroll
            for (int j = 0; j < 8; j++) {
                int idx = lane * 8 + j;
                int rr = idx >> 4, cc = idx & 15;
                int lr = m0 + r0 + rr;
                if (lr < cnt) {
                    int tok  = g_tok[e][lr];
                    float gt = g_gate[e][lr];
                    float v  = Cw[rr * 24 + cc] + b2e[c0g + cc];
                    atomicAdd(&out[(size_t)tok * DMODEL + c0g + cc], gt * v);
                }
            }
            __syncwarp();
        }
    }
}

// ---------------- launch ----------------
extern "C" void kernel_launch(void* const* d_in, const int* in_sizes, int n_in,
                              void* d_out, int out_size)
{
    const float* x    = (const float*)d_in[0];
    const float* dt   = (const float*)d_in[1];
    const float* dd   = (const float*)d_in[2];
    const float* drg  = (const float*)d_in[3];
    const float* de   = (const float*)d_in[4];
    const float* city = (const float*)d_in[5];
    const float* Wg   = (const float*)d_in[6];
    const float* bg   = (const float*)d_in[7];
    const float* W1   = (const float*)d_in[8];
    const float* b1   = (const float*)d_in[9];
    const float* W2   = (const float*)d_in[10];
    const float* b2   = (const float*)d_in[11];
    const int*   cidx = (const int*)  d_in[12];

    float* out   = (float*)d_out;
    float* gate1 = out + OUT_ELEMS;

    cudaFuncSetAttribute(ffn1_kernel, cudaFuncAttributeMaxDynamicSharedMemorySize, SMEM_BYTES);
    cudaFuncSetAttribute(ffn2_kernel, cudaFuncAttributeMaxDynamicSharedMemorySize, SMEM_BYTES);

    void* cnt_ptr = nullptr; cudaGetSymbolAddress(&cnt_ptr, g_cnt);
    void* xr_ptr  = nullptr; cudaGetSymbolAddress(&xr_ptr,  g_xr);
    void* w1r_ptr = nullptr; cudaGetSymbolAddress(&w1r_ptr, g_w1r);
    void* w2r_ptr = nullptr; cudaGetSymbolAddress(&w2r_ptr, g_w2r);

    cudaMemsetAsync(cnt_ptr, 0, sizeof(int) * NE, 0);
    cudaMemsetAsync(out, 0, OUT_ELEMS * sizeof(float), 0);

    // tf32-RN pre-rounding (gating still reads original fp32 x)
    round_copy_kernel<<<(NTOK * DMODEL / 4) / 256, 256>>>(x, (float*)xr_ptr);
    round_copy_kernel<<<((size_t)NE * DMODEL * DFF / 4) / 256, 256>>>(W1, (float*)w1r_ptr);
    round_copy_kernel<<<((size_t)NE * DFF * DMODEL / 4) / 256, 256>>>(W2, (float*)w2r_ptr);

    gating_kernel<<<NTOK, 256>>>(x, dt, dd, drg, de, city, Wg, bg, cidx, gate1);
    schedule_kernel<<<1, 32>>>();

    dim3 g1(MAXTILES, DFF / 128);      // (136, 32)
    dim3 g2(MAXTILES, DMODEL / 128);   // (136, 8)
    ffn1_kernel<<<g1, 256, SMEM_BYTES>>>(b1);
    ffn2_kernel<<<g2, 256, SMEM_BYTES>>>(b2, out);
}

// round 14
// speedup vs baseline: 3.2167x; 1.9293x over previous
#include <cuda_runtime.h>
#include <math.h>
#include <stdint.h>

#define NTOK   8192
#define NE     8
#define DMODEL 1024
#define DFF    4096
#define OUT_ELEMS ((size_t)NTOK * DMODEL)
#define MAXROWS (NTOK * 2)
#define MAXTILES 136

// ---------------- device scratch ----------------
__device__ int   g_cnt[NE];
__device__ int   g_off[NE + 1];
__device__ int   g_tok[NE][NTOK];
__device__ float g_gate[NE][NTOK];
__device__ int   g_tile_e[MAXTILES];
__device__ int   g_tile_m0[MAXTILES];
__device__ int   g_ntiles;
__device__ float g_hbuf[(size_t)(MAXROWS + 128) * DFF];   // tf32-RN h scratch (+pad rows)
__device__ float g_xr[(size_t)NTOK * DMODEL];             // tf32-RN x
__device__ float g_w1t[(size_t)NE * DFF * DMODEL];        // W1 transposed [e][n:4096][k:1024], tf32-RN
__device__ float g_w2t[(size_t)NE * DMODEL * DFF];        // W2 transposed [e][n:1024][k:4096], tf32-RN

// ---------------- helpers ----------------
__device__ __forceinline__ unsigned smem_u32(const void* p) {
    return (unsigned)__cvta_generic_to_shared(p);
}
__device__ __forceinline__ void cp_async16(uint32_t dst_smem, const void* src_gmem) {
    asm volatile("cp.async.cg.shared.global [%0], [%1], 16;\n"
                 :: "r"(dst_smem), "l"(src_gmem));
}
__device__ __forceinline__ void cp_commit() { asm volatile("cp.async.commit_group;\n"); }
template<int N> __device__ __forceinline__ void cp_wait() {
    asm volatile("cp.async.wait_group %0;\n" :: "n"(N));
}
__device__ __forceinline__ float to_tf32(float x) {
    float r;
    asm("cvt.rna.tf32.f32 %0, %1;" : "=f"(r) : "f"(x));
    return r;
}
__device__ __forceinline__ float gelu_f(float v) {
    float u = 0.7978845608028654f * (v + 0.044715f * v * v * v);
    return v / (1.0f + __expf(-2.0f * u));   // == 0.5*v*(1+tanh(u))
}
// ldmatrix x4 (b16 view of tf32 tiles)
__device__ __forceinline__ void ldsm4(uint32_t& r0, uint32_t& r1, uint32_t& r2, uint32_t& r3,
                                      uint32_t addr) {
    asm volatile("ldmatrix.sync.aligned.m8n8.x4.shared.b16 {%0,%1,%2,%3}, [%4];"
                 : "=r"(r0), "=r"(r1), "=r"(r2), "=r"(r3) : "r"(addr));
}
__device__ __forceinline__ void mma_tf32(float& d0, float& d1, float& d2, float& d3,
                                         uint32_t a0, uint32_t a1, uint32_t a2, uint32_t a3,
                                         uint32_t b0, uint32_t b1) {
    asm volatile("mma.sync.aligned.m16n8k8.row.col.f32.tf32.tf32.f32 "
                 "{%0,%1,%2,%3}, {%4,%5,%6,%7}, {%8,%9}, {%0,%1,%2,%3};\n"
                 : "+f"(d0), "+f"(d1), "+f"(d2), "+f"(d3)
                 : "r"(a0), "r"(a1), "r"(a2), "r"(a3), "r"(b0), "r"(b1));
}

// ---------------- x rounding (+ g_cnt zero) ----------------
__global__ void round_x_kernel(const float* __restrict__ x, float* __restrict__ xr)
{
    if (blockIdx.x == 0 && threadIdx.x < NE) g_cnt[threadIdx.x] = 0;
    size_t i = (size_t)blockIdx.x * blockDim.x + threadIdx.x;
    float4 v = ((const float4*)x)[i];
    v.x = to_tf32(v.x); v.y = to_tf32(v.y); v.z = to_tf32(v.z); v.w = to_tf32(v.w);
    ((float4*)xr)[i] = v;
}

// ---------------- weight transpose + tf32-RN: src[R][C] -> dst[C][R] ----------------
__global__ void transpose_kernel(const float* __restrict__ src, float* __restrict__ dst,
                                 int R, int C)
{
    __shared__ float t[32][33];
    size_t eo = (size_t)blockIdx.z * R * C;
    const float* s = src + eo;
    float* d = dst + eo;
    int c0 = blockIdx.x * 32, r0 = blockIdx.y * 32;
    int tx = threadIdx.x, ty = threadIdx.y;
    #pragma unroll
    for (int j = 0; j < 32; j += 8)
        t[ty + j][tx] = to_tf32(s[(size_t)(r0 + ty + j) * C + c0 + tx]);
    __syncthreads();
    #pragma unroll
    for (int j = 0; j < 32; j += 8)
        d[(size_t)(c0 + ty + j) * R + r0 + tx] = t[tx][ty + j];
}

// ---------------- gating (also zeroes its token's out row) ----------------
__device__ __forceinline__ void accum_seg(const float* __restrict__ f, int len,
                                          const float* __restrict__ wg_base,
                                          float acc[8], int tid)
{
    for (int l = tid; l < len; l += 256) {
        float v = f[l];
        const float4* w = (const float4*)(wg_base + (size_t)l * 8);
        float4 w0 = w[0], w1 = w[1];
        acc[0] += v * w0.x; acc[1] += v * w0.y; acc[2] += v * w0.z; acc[3] += v * w0.w;
        acc[4] += v * w1.x; acc[5] += v * w1.y; acc[6] += v * w1.z; acc[7] += v * w1.w;
    }
}

__global__ void gating_kernel(const float* __restrict__ x,
                              const float* __restrict__ dt,
                              const float* __restrict__ dd,
                              const float* __restrict__ drg,
                              const float* __restrict__ de,
                              const float* __restrict__ city,
                              const float* __restrict__ Wg,
                              const float* __restrict__ bg,
                              const int*   __restrict__ city_index,
                              float* __restrict__ out,
                              float* __restrict__ gate1_out)
{
    int t = blockIdx.x;
    int tid = threadIdx.x;

    // zero this token's output row (replaces cudaMemsetAsync)
    ((float4*)(out + (size_t)t * DMODEL))[tid] = make_float4(0.f, 0.f, 0.f, 0.f);

    float acc[8] = {0,0,0,0,0,0,0,0};
    const float* cemb = city + (*city_index) * 32;

    accum_seg(x   + (size_t)t * 1024, 1024, Wg + (size_t)0    * 8, acc, tid);
    accum_seg(cemb,                     32, Wg + (size_t)1024 * 8, acc, tid);
    accum_seg(dt  + (size_t)t * 256,   256, Wg + (size_t)1056 * 8, acc, tid);
    accum_seg(dd  + (size_t)t * 256,   256, Wg + (size_t)1312 * 8, acc, tid);
    accum_seg(drg + (size_t)t * 128,   128, Wg + (size_t)1568 * 8, acc, tid);
    accum_seg(de  + (size_t)t * 128,   128, Wg + (size_t)1696 * 8, acc, tid);

    __shared__ float red[8][256];
    #pragma unroll
    for (int e = 0; e < 8; e++) red[e][tid] = acc[e];
    __syncthreads();
    for (int s = 128; s > 0; s >>= 1) {
        if (tid < s) {
            #pragma unroll
            for (int e = 0; e < 8; e++) red[e][tid] += red[e][tid + s];
        }
        __syncthreads();
    }

    if (tid == 0) {
        float lg[8];
        #pragma unroll
        for (int e = 0; e < 8; e++) lg[e] = red[e][0] + bg[e];

        float l0 = lg[0]; int i0 = 0;
        #pragma unroll
        for (int e = 1; e < 8; e++) if (lg[e] > l0) { l0 = lg[e]; i0 = e; }
        float l1 = -1e30f; int i1 = -1;
        #pragma unroll
        for (int e = 0; e < 8; e++) if (e != i0 && lg[e] > l1) { l1 = lg[e]; i1 = e; }

        float ssum = 0.f, ex[8];
        #pragma unroll
        for (int e = 0; e < 8; e++) { ex[e] = __expf(lg[e] - l0); ssum += ex[e]; }
        float inv = 1.0f / ssum;
        #pragma unroll
        for (int e = 0; e < 8; e++) gate1_out[(size_t)t * 8 + e] = ex[e] * inv;

        float e1 = __expf(l1 - l0);
        float g0 = 1.0f / (1.0f + e1);
        float g1 = e1   / (1.0f + e1);

        int p0 = atomicAdd(&g_cnt[i0], 1);
        g_tok[i0][p0] = t; g_gate[i0][p0] = g0;
        int p1 = atomicAdd(&g_cnt[i1], 1);
        g_tok[i1][p1] = t; g_gate[i1][p1] = g1;
    }
}

__global__ void schedule_kernel()
{
    if (threadIdx.x == 0 && blockIdx.x == 0) {
        int off = 0, nt = 0;
        for (int e = 0; e < NE; e++) {
            g_off[e] = off;
            int c = g_cnt[e];
            int t = (c + 127) >> 7;
            for (int i = 0; i < t; i++) { g_tile_e[nt] = e; g_tile_m0[nt] = i << 7; nt++; }
            off += c;
        }
        g_off[NE] = off;
        g_ntiles = nt;
    }
}

// ---------------- ldmatrix-fed tf32 GEMM ----------------
// Block 128x128x32, 8 warps (2x4), warp tile 64x32 (mma m16n8k8).
// A smem [m:128][k:32] stride 36; B smem [n:128][k:32] stride 36 (weights pre-transposed).
// 3-stage cp.async pipeline; fragments via ldmatrix.x4 (tf32-as-b16 trick).

#define T_LD 36
#define T_ELEMS (128 * T_LD)                 // 4608 floats per A or B tile
#define STAGE_ELEMS (2 * T_ELEMS)            // 9216
#define NSTAGE 3
#define SMEM_BYTES (NSTAGE * STAGE_ELEMS * 4)   // 110592

__device__ __forceinline__ void issue_stage(uint32_t As, uint32_t Bs,
                                            const float* __restrict__ a_base, int k0,
                                            const float* __restrict__ wt_base, int KDIM,
                                            int tid)
{
    int r    = tid >> 1;              // 0..127 (row in A and n-row in B)
    int seg  = (tid & 1) * 16;        // 0 or 16 floats
    const float* ap = a_base + k0 + seg;
    uint32_t ad = As + (r * T_LD + seg) * 4;
    cp_async16(ad +  0, ap +  0);
    cp_async16(ad + 16, ap +  4);
    cp_async16(ad + 32, ap +  8);
    cp_async16(ad + 48, ap + 12);
    const float* bp = wt_base + (size_t)r * KDIM + k0 + seg;
    uint32_t bd = Bs + (r * T_LD + seg) * 4;
    cp_async16(bd +  0, bp +  0);
    cp_async16(bd + 16, bp +  4);
    cp_async16(bd + 32, bp +  8);
    cp_async16(bd + 48, bp + 12);
}

template<int KDIM>
__device__ __forceinline__ void gemm_mainloop(
    uint32_t sb,
    const float* __restrict__ a_base,   // per-thread gathered A row base (row tid>>1)
    const float* __restrict__ wt_base,  // transposed weights + n0 rows, [n][KDIM]
    int tid, int wm, int wn, int lane,
    float (&d)[4][4][4])
{
    const int KT = KDIM / 32;

    uint32_t As[NSTAGE], Bs[NSTAGE];
    #pragma unroll
    for (int s = 0; s < NSTAGE; s++) {
        As[s] = sb + s * (STAGE_ELEMS * 4);
        Bs[s] = As[s] + T_ELEMS * 4;
    }

    // ldmatrix per-lane address components (float offsets)
    int a_row = (lane & 15);            // row within m16 tile
    int a_kof = (lane >> 4) * 4;        // k offset 0 or 4
    int b_row = (lane & 7) | ((lane >> 1) & 8);   // n within n16 pair-group
    int b_kof = ((lane >> 3) & 1) * 4;  // k offset 0 or 4

    issue_stage(As[0], Bs[0], a_base, 0,  wt_base, KDIM, tid);
    cp_commit();
    issue_stage(As[1], Bs[1], a_base, 32, wt_base, KDIM, tid);
    cp_commit();

    for (int kt = 0; kt < KT; kt++) {
        cp_wait<1>();
        __syncthreads();

        int ks2 = kt + 2;
        if (ks2 < KT) {
            int buf = ks2 % NSTAGE;
            issue_stage(As[buf], Bs[buf], a_base, ks2 * 32, wt_base, KDIM, tid);
        }
        cp_commit();

        uint32_t Ac = As[kt % NSTAGE];
        uint32_t Bc = Bs[kt % NSTAGE];
        uint32_t a_addr0 = Ac + ((wm * 64 + a_row) * T_LD + a_kof) * 4;
        uint32_t b_addr0 = Bc + ((wn * 32 + b_row) * T_LD + b_kof) * 4;

        #pragma unroll
        for (int ks = 0; ks < 32; ks += 8) {
            uint32_t a[4][4];
            #pragma unroll
            for (int mi = 0; mi < 4; mi++)
                ldsm4(a[mi][0], a[mi][1], a[mi][2], a[mi][3],
                      a_addr0 + (mi * 16 * T_LD + ks) * 4);
            uint32_t b[2][4];
            #pragma unroll
            for (int nb = 0; nb < 2; nb++)
                ldsm4(b[nb][0], b[nb][1], b[nb][2], b[nb][3],
                      b_addr0 + (nb * 16 * T_LD + ks) * 4);
            #pragma unroll
            for (int mi = 0; mi < 4; mi++) {
                #pragma unroll
                for (int ni = 0; ni < 4; ni++) {
                    uint32_t b0 = b[ni >> 1][(ni & 1) * 2];
                    uint32_t b1 = b[ni >> 1][(ni & 1) * 2 + 1];
                    mma_tf32(d[mi][ni][0], d[mi][ni][1], d[mi][ni][2], d[mi][ni][3],
                             a[mi][0], a[mi][1], a[mi][2], a[mi][3], b0, b1);
                }
            }
        }
    }
    __syncthreads();
}

__global__ void __launch_bounds__(256, 2)
ffn1_kernel(const float* __restrict__ b1)
{
    extern __shared__ float smem[];
    uint32_t sb = smem_u32(smem);

    int tile = blockIdx.x;
    if (tile >= g_ntiles) return;
    int e = g_tile_e[tile], m0 = g_tile_m0[tile], cnt = g_cnt[e];
    int gbase = g_off[e] + m0;
    int n0 = blockIdx.y * 128;

    int tid = threadIdx.x, warp = tid >> 5, lane = tid & 31;
    int wm = warp >> 2, wn = warp & 3;
    int g = lane >> 2, tq = lane & 3;

    int ar = tid >> 1;
    int lrow = m0 + ar;
    int tok = g_tok[e][lrow < cnt ? lrow : (cnt - 1)];
    const float* a_base = g_xr + (size_t)tok * DMODEL;
    const float* wt_base = g_w1t + ((size_t)e * DFF + n0) * DMODEL;

    float d[4][4][4];
    #pragma unroll
    for (int mi = 0; mi < 4; mi++)
        #pragma unroll
        for (int ni = 0; ni < 4; ni++)
            #pragma unroll
            for (int k = 0; k < 4; k++) d[mi][ni][k] = 0.f;

    gemm_mainloop<DMODEL>(sb, a_base, wt_base, tid, wm, wn, lane, d);

    // epilogue: + b1, GELU, tf32-RN, direct global write (no smem staging)
    const float* b1e = b1 + (size_t)e * DFF;
    float2 bias[4];
    #pragma unroll
    for (int ni = 0; ni < 4; ni++) {
        int c = n0 + wn * 32 + ni * 8 + 2 * tq;
        bias[ni] = make_float2(b1e[c], b1e[c + 1]);
    }
    #pragma unroll
    for (int mi = 0; mi < 4; mi++) {
        int rl0 = wm * 64 + mi * 16 + g;       // local rows rl0 and rl0+8
        #pragma unroll
        for (int half = 0; half < 2; half++) {
            int rl = rl0 + half * 8;
            if (m0 + rl < cnt) {
                float* dst = g_hbuf + (size_t)(gbase + rl) * DFF + n0 + wn * 32;
                #pragma unroll
                for (int ni = 0; ni < 4; ni++) {
                    float v0 = d[mi][ni][half * 2 + 0] + bias[ni].x;
                    float v1 = d[mi][ni][half * 2 + 1] + bias[ni].y;
                    float2 o = make_float2(to_tf32(gelu_f(v0)), to_tf32(gelu_f(v1)));
                    *(float2*)(dst + ni * 8 + 2 * tq) = o;
                }
            }
        }
    }
}

__global__ void __launch_bounds__(256, 2)
ffn2_kernel(const float* __restrict__ b2, float* __restrict__ out)
{
    extern __shared__ float smem[];
    uint32_t sb = smem_u32(smem);

    int tile = blockIdx.x;
    if (tile >= g_ntiles) return;
    int e = g_tile_e[tile], m0 = g_tile_m0[tile], cnt = g_cnt[e];
    int gbase = g_off[e] + m0;
    int n0 = blockIdx.y * 128;

    int tid = threadIdx.x, warp = tid >> 5, lane = tid & 31;
    int wm = warp >> 2, wn = warp & 3;
    int g = lane >> 2, tq = lane & 3;

    int ar = tid >> 1;
    const float* a_base = g_hbuf + (size_t)(gbase + ar) * DFF;
    const float* wt_base = g_w2t + ((size_t)e * DMODEL + n0) * DFF;

    float d[4][4][4];
    #pragma unroll
    for (int mi = 0; mi < 4; mi++)
        #pragma unroll
        for (int ni = 0; ni < 4; ni++)
            #pragma unroll
            for (int k = 0; k < 4; k++) d[mi][ni][k] = 0.f;

    gemm_mainloop<DFF>(sb, a_base, wt_base, tid, wm, wn, lane, d);

    const float* b2e = b2 + (size_t)e * DMODEL;
    float2 bias[4];
    #pragma unroll
    for (int ni = 0; ni < 4; ni++) {
        int c = n0 + wn * 32 + ni * 8 + 2 * tq;
        bias[ni] = make_float2(b2e[c], b2e[c + 1]);
    }
    #pragma unroll
    for (int mi = 0; mi < 4; mi++) {
        int rl0 = wm * 64 + mi * 16 + g;
        #pragma unroll
        for (int half = 0; half < 2; half++) {
            int rl = rl0 + half * 8;
            if (m0 + rl < cnt) {
                int tok  = g_tok[e][m0 + rl];
                float gt = g_gate[e][m0 + rl];
                float* op = out + (size_t)tok * DMODEL + n0 + wn * 32;
                #pragma unroll
                for (int ni = 0; ni < 4; ni++) {
                    float v0 = d[mi][ni][half * 2 + 0] + bias[ni].x;
                    float v1 = d[mi][ni][half * 2 + 1] + bias[ni].y;
                    atomicAdd(op + ni * 8 + 2 * tq,     gt * v0);
                    atomicAdd(op + ni * 8 + 2 * tq + 1, gt * v1);
                }
            }
        }
    }
}

// ---------------- launch ----------------
// Launch order puts ffn1 at index 5 so ncu (-s 5 -c 1) profiles it next round.
extern "C" void kernel_launch(void* const* d_in, const int* in_sizes, int n_in,
                              void* d_out, int out_size)
{
    const float* x    = (const float*)d_in[0];
    const float* dt   = (const float*)d_in[1];
    const float* dd   = (const float*)d_in[2];
    const float* drg  = (const float*)d_in[3];
    const float* de   = (const float*)d_in[4];
    const float* city = (const float*)d_in[5];
    const float* Wg   = (const float*)d_in[6];
    const float* bg   = (const float*)d_in[7];
    const float* W1   = (const float*)d_in[8];
    const float* b1   = (const float*)d_in[9];
    const float* W2   = (const float*)d_in[10];
    const float* b2   = (const float*)d_in[11];
    const int*   cidx = (const int*)  d_in[12];

    float* out   = (float*)d_out;
    float* gate1 = out + OUT_ELEMS;

    cudaFuncSetAttribute(ffn1_kernel, cudaFuncAttributeMaxDynamicSharedMemorySize, SMEM_BYTES);
    cudaFuncSetAttribute(ffn2_kernel, cudaFuncAttributeMaxDynamicSharedMemorySize, SMEM_BYTES);

    void* xr_ptr  = nullptr; cudaGetSymbolAddress(&xr_ptr,  g_xr);
    void* w1t_ptr = nullptr; cudaGetSymbolAddress(&w1t_ptr, g_w1t);
    void* w2t_ptr = nullptr; cudaGetSymbolAddress(&w2t_ptr, g_w2t);

    // 0: x tf32-round (+ g_cnt zero)
    round_x_kernel<<<(NTOK * DMODEL / 4) / 256, 256>>>(x, (float*)xr_ptr);
    // 1,2: weight transpose + tf32-round -> [n][k]
    transpose_kernel<<<dim3(DFF / 32, DMODEL / 32, NE), dim3(32, 8)>>>(W1, (float*)w1t_ptr, DMODEL, DFF);
    transpose_kernel<<<dim3(DMODEL / 32, DFF / 32, NE), dim3(32, 8)>>>(W2, (float*)w2t_ptr, DFF, DMODEL);
    // 3: gating (+ out zero)
    gating_kernel<<<NTOK, 256>>>(x, dt, dd, drg, de, city, Wg, bg, cidx, out, gate1);
    // 4: schedule
    schedule_kernel<<<1, 32>>>();
    // 5: ffn1 (ncu target), 6: ffn2
    ffn1_kernel<<<dim3(MAXTILES, DFF / 128), 256, SMEM_BYTES>>>(b1);
    ffn2_kernel<<<dim3(MAXTILES, DMODEL / 128), 256, SMEM_BYTES>>>(b2, out);
}